// round 2
// baseline (speedup 1.0000x reference)
#include <cuda_runtime.h>
#include <cuda_bf16.h>

// EMA over time axis for wave[B=4096, T=6000, C=3] fp32, w = 0.6.
// sta_t = sta_{t-1} + w*(x_t - sta_{t-1}), sta_{-1} = 0.
// Key fact: (1-w)^32 = 0.4^32 ~ 1.8e-13 << fp32 eps, so a 32-step warm-up
// window reproduces the exact scan to machine precision -> fully parallel.

#define B_DIM 4096
#define T_DIM 6000
#define C_DIM 3
#define TC    (T_DIM * C_DIM)      // 18000 floats per batch row
#define WEMA  0.6f

#define NT    128                  // threads per CTA
#define CH    11                   // timesteps emitted per thread (3*CH=33 -> bank-conflict-free)
#define S_T   (NT * CH)            // 1408 timesteps per tile
#define WARM  32                   // warm-up timesteps
#define TILES ((T_DIM + S_T - 1) / S_T)   // 5

#define BUF_F ((S_T + WARM) * C_DIM)      // 4320 floats in smem
#define NVEC_LD (BUF_F / 4)               // 1080 float4 loads
#define NVEC_ST ((S_T * C_DIM) / 4)       // 1056 float4 stores

__global__ __launch_bounds__(NT, 8)
void sta_ema_kernel(const float* __restrict__ in, float* __restrict__ out) {
    __shared__ float buf[BUF_F];

    const int tid  = threadIdx.x;
    const int tile = blockIdx.x;
    const int b    = blockIdx.y;

    const float* src = in  + (long long)b * TC;
    float*       dst = out + (long long)b * TC;

    const int t0 = tile * S_T;          // first timestep this tile emits
    const int g0 = t0 - WARM;           // first timestep loaded (may be < 0)
    const int f0 = g0 * C_DIM;          // first float loaded; multiple of 4 (4224*tile - 96)

    // ---- Coalesced vector load of [g0, g0 + S_T + WARM) timesteps ----
    // f0 and all f are multiples of 4, TC = 18000 is a multiple of 4,
    // so bounds checks are whole-float4 (all-in or all-out).
    #pragma unroll 4
    for (int u = tid; u < NVEC_LD; u += NT) {
        const int f = f0 + 4 * u;
        float4 v;
        if (f >= 0 && f < TC) {
            v = *reinterpret_cast<const float4*>(src + f);
        } else {
            v = make_float4(0.f, 0.f, 0.f, 0.f);
        }
        *reinterpret_cast<float4*>(buf + 4 * u) = v;
    }
    __syncthreads();

    // ---- Windowed scan: 32-step warm-up + 11 emitted steps, all in smem ----
    // Thread k reads smem floats at (k*CH + s)*3 + c: inter-thread stride 33
    // floats == 1 mod 32 banks -> conflict-free.
    float s0 = 0.f, s1 = 0.f, s2 = 0.f;
    const float* p = buf + tid * CH * C_DIM;

    #pragma unroll
    for (int i = 0; i < WARM; ++i) {
        s0 += WEMA * (p[0] - s0);
        s1 += WEMA * (p[1] - s1);
        s2 += WEMA * (p[2] - s2);
        p += C_DIM;
    }

    float o[CH * C_DIM];
    #pragma unroll
    for (int i = 0; i < CH; ++i) {
        s0 += WEMA * (p[0] - s0);
        s1 += WEMA * (p[1] - s1);
        s2 += WEMA * (p[2] - s2);
        o[i * C_DIM + 0] = s0;
        o[i * C_DIM + 1] = s1;
        o[i * C_DIM + 2] = s2;
        p += C_DIM;
    }

    __syncthreads();   // all warm-up reads done before overwriting tile region

    // ---- Stage results back into smem (same conflict-free stride) ----
    float* q = buf + (WARM + tid * CH) * C_DIM;
    #pragma unroll
    for (int i = 0; i < CH * C_DIM; ++i) q[i] = o[i];

    __syncthreads();

    // ---- Coalesced vector store of emitted region [t0, t0 + S_T) ----
    const int fo0 = t0 * C_DIM;         // multiple of 4 (4224*tile)
    #pragma unroll 4
    for (int u = tid; u < NVEC_ST; u += NT) {
        const int f = fo0 + 4 * u;
        if (f < TC) {
            *reinterpret_cast<float4*>(dst + f) =
                *reinterpret_cast<const float4*>(buf + WARM * C_DIM + 4 * u);
        }
    }
}

extern "C" void kernel_launch(void* const* d_in, const int* in_sizes, int n_in,
                              void* d_out, int out_size) {
    const float* in  = (const float*)d_in[0];
    float*       out = (float*)d_out;
    dim3 grid(TILES, B_DIM, 1);
    sta_ema_kernel<<<grid, NT>>>(in, out);
}

// round 3
// speedup vs baseline: 1.0551x; 1.0551x over previous
#include <cuda_runtime.h>
#include <cuda_bf16.h>

// EMA over time axis for wave[B=4096, T=6000, C=3] fp32, w = 0.6.
// sta_t = sta_{t-1} + w*(x_t - sta_{t-1}), sta_{-1} = 0.
// (1-w)^16 = 0.4^16 ~ 4.3e-7, so a 16-step warm-up window reproduces the scan
// to ~1e-6 relative -- far below the 1e-3 gate -> fully parallel windows.

#define B_DIM 4096
#define T_DIM 6000
#define C_DIM 3
#define TC    (T_DIM * C_DIM)      // 18000 floats per batch row
#define WEMA  0.6f

#define NT    128                  // threads per CTA
#define CH    15                   // timesteps emitted per thread (3*CH=45, 45%32=13 odd -> conflict-free)
#define S_T   (NT * CH)            // 1920 timesteps per tile
#define WARM  16                   // warm-up timesteps (0.4^16 ~ 4.3e-7)
#define TILES ((T_DIM + S_T - 1) / S_T)   // 4 (covers 7680; tail guarded)

#define BUF_F ((S_T + WARM) * C_DIM)      // 5808 floats (23.2 KB smem)
#define NVEC_LD (BUF_F / 4)               // 1452 float4 loads
#define NVEC_ST ((S_T * C_DIM) / 4)       // 1440 float4 stores

__global__ __launch_bounds__(NT, 8)
void sta_ema_kernel(const float* __restrict__ in, float* __restrict__ out) {
    __shared__ float buf[BUF_F];

    const int tid  = threadIdx.x;
    const int tile = blockIdx.x;
    const int b    = blockIdx.y;

    const float* src = in  + (long long)b * TC;
    float*       dst = out + (long long)b * TC;

    const int t0 = tile * S_T;          // first timestep this tile emits
    const int f0 = t0 * C_DIM - WARM * C_DIM;  // first float loaded (mult of 4: 5760*tile - 48)

    // ---- Coalesced vector load of [t0-WARM, t0+S_T) timesteps ----
    // All float4 offsets are multiples of 4; TC = 18000 is too, so bounds
    // checks are whole-float4 (all-in or all-out).
    #pragma unroll 4
    for (int u = tid; u < NVEC_LD; u += NT) {
        const int f = f0 + 4 * u;
        float4 v;
        if (f >= 0 && f < TC) {
            v = *reinterpret_cast<const float4*>(src + f);
        } else {
            v = make_float4(0.f, 0.f, 0.f, 0.f);
        }
        *reinterpret_cast<float4*>(buf + 4 * u) = v;
    }
    __syncthreads();

    // ---- Windowed scan: 16-step warm-up + 15 emitted steps, all in smem ----
    // Thread k reads floats at (k*CH + s)*3 + c: inter-thread stride 45
    // floats == 13 mod 32 banks (odd) -> conflict-free.
    float s0 = 0.f, s1 = 0.f, s2 = 0.f;
    const float* p = buf + tid * CH * C_DIM;

    #pragma unroll
    for (int i = 0; i < WARM; ++i) {
        s0 = fmaf(WEMA, p[0] - s0, s0);
        s1 = fmaf(WEMA, p[1] - s1, s1);
        s2 = fmaf(WEMA, p[2] - s2, s2);
        p += C_DIM;
    }

    float o[CH * C_DIM];
    #pragma unroll
    for (int i = 0; i < CH; ++i) {
        s0 = fmaf(WEMA, p[0] - s0, s0);
        s1 = fmaf(WEMA, p[1] - s1, s1);
        s2 = fmaf(WEMA, p[2] - s2, s2);
        o[i * C_DIM + 0] = s0;
        o[i * C_DIM + 1] = s1;
        o[i * C_DIM + 2] = s2;
        p += C_DIM;
    }

    __syncthreads();   // all warm-up reads done before overwriting tile region

    // ---- Stage results back into smem (same conflict-free stride) ----
    float* q = buf + (WARM + tid * CH) * C_DIM;
    #pragma unroll
    for (int i = 0; i < CH * C_DIM; ++i) q[i] = o[i];

    __syncthreads();

    // ---- Coalesced vector store of emitted region [t0, t0 + S_T) ----
    const int fo0 = t0 * C_DIM;         // multiple of 4 (5760*tile)
    #pragma unroll 4
    for (int u = tid; u < NVEC_ST; u += NT) {
        const int f = fo0 + 4 * u;
        if (f < TC) {
            *reinterpret_cast<float4*>(dst + f) =
                *reinterpret_cast<const float4*>(buf + WARM * C_DIM + 4 * u);
        }
    }
}

extern "C" void kernel_launch(void* const* d_in, const int* in_sizes, int n_in,
                              void* d_out, int out_size) {
    const float* in  = (const float*)d_in[0];
    float*       out = (float*)d_out;
    dim3 grid(TILES, B_DIM, 1);
    sta_ema_kernel<<<grid, NT>>>(in, out);
}

// round 5
// speedup vs baseline: 1.1660x; 1.1051x over previous
#include <cuda_runtime.h>
#include <cuda_bf16.h>

// EMA over time for wave[B=4096, T=6000, C=3] fp32, w=0.6, a=1-w=0.4.
//   y[f] = a*y[f-3] + w*x[f]   (per-channel recurrence; y[f<0]=0)
//
// Register-only formulation: one float4 group g (floats 4g..4g+3) maps the
// 3-float sliding state s=(y[4g-3],y[4g-2],y[4g-1]) to s'=(y[4g+1..4g+3]):
//   s' = A s + b(x),  A = a*S,  S = [[0,1,0],[0,0,1],[a,0,0]],  S^3 = a*I
//   b(x) = (w*x1, w*x2, a*w*x0 + w*x3)
// Lane k of a warp handles group 32*i + k -> perfectly coalesced float4 I/O.
// Warp-level affine scan (steps d=1,2,4,8; A^16 entries ~1e-8 -> dropped)
// + per-lane constant carry matrix A^(k+1) folds in all older history.

#define A1  0.4f
#define WW  0.6f
#define A2  (A1*A1)
#define A3  (A2*A1)
#define A5  (A2*A3)
#define A6  (A3*A3)
#define A10 (A5*A5)
#define A11 (A5*A6)

#define B_DIM   4096
#define ROW_F4  4500            // 18000 floats / 4 per batch row
#define ITERS   141             // ceil(4500/32) warp iterations per row
#define SEGJ    24              // emit-iterations per warp segment
#define NSEG    6               // ceil(141/24)
#define NT      256
#define FULLM   0xFFFFFFFFu

__global__ __launch_bounds__(NT, 8)
void sta_ema_scan_kernel(const float4* __restrict__ in, float4* __restrict__ out) {
    const int gw   = (blockIdx.x * NT + threadIdx.x) >> 5;   // global warp id
    const int lane = threadIdx.x & 31;
    if (gw >= B_DIM * NSEG) return;

    const int b = gw / NSEG;
    const int s = gw % NSEG;

    const float4* src = in  + (long long)b * ROW_F4;
    float4*       dst = out + (long long)b * ROW_F4;

    const int i0 = SEGJ * s;
    const int i1 = min(i0 + SEGJ, ITERS);
    const int istart = (s > 0) ? (i0 - 1) : i0;   // warm iteration (no store)

    // Per-lane constant carry matrix A^(k+1) = a^(k+1) * S^(k+1),
    // S^(k+1) = a^floor((k+1)/3) * S^((k+1)%3).
    const int  kp = lane + 1;
    const int  m  = kp / 3;
    const int  r  = kp % 3;
    const float gamma = __powf(A1, (float)(kp + m));
    float g0 = gamma, g1 = gamma, g2 = gamma;
    if (r == 1) { g2 *= A1; }
    if (r == 2) { g1 *= A1; g2 *= A1; }

    float sc0 = 0.f, sc1 = 0.f, sc2 = 0.f;       // carry: state before this iter's groups

    for (int i = istart; i < i1; ++i) {
        const int q = 32 * i + lane;             // float4 index within row
        const bool valid = (q < ROW_F4);
        float4 x = valid ? src[q] : make_float4(0.f, 0.f, 0.f, 0.f);

        // local affine offset b(x)
        float v0 = WW * x.y;
        float v1 = WW * x.z;
        float v2 = fmaf(A1 * WW, x.x, WW * x.w);

        // ---- affine scan across lanes: v_k = sum_{j<=k} A^(k-j) b_j ----
        float t0, t1, t2;
        // d = 1 : A^1 = a*S       -> (a*t1, a*t2, a^2*t0)
        t0 = __shfl_up_sync(FULLM, v0, 1);
        t1 = __shfl_up_sync(FULLM, v1, 1);
        t2 = __shfl_up_sync(FULLM, v2, 1);
        if (lane < 1) { t0 = 0.f; t1 = 0.f; t2 = 0.f; }
        v0 = fmaf(A1, t1, v0);  v1 = fmaf(A1, t2, v1);  v2 = fmaf(A2, t0, v2);
        // d = 2 : A^2 = a^2*S^2   -> (a^2*t2, a^3*t0, a^3*t1)
        t0 = __shfl_up_sync(FULLM, v0, 2);
        t1 = __shfl_up_sync(FULLM, v1, 2);
        t2 = __shfl_up_sync(FULLM, v2, 2);
        if (lane < 2) { t0 = 0.f; t1 = 0.f; t2 = 0.f; }
        v0 = fmaf(A2, t2, v0);  v1 = fmaf(A3, t0, v1);  v2 = fmaf(A3, t1, v2);
        // d = 4 : A^4 = a^5*S     -> (a^5*t1, a^5*t2, a^6*t0)
        t0 = __shfl_up_sync(FULLM, v0, 4);
        t1 = __shfl_up_sync(FULLM, v1, 4);
        t2 = __shfl_up_sync(FULLM, v2, 4);
        if (lane < 4) { t0 = 0.f; t1 = 0.f; t2 = 0.f; }
        v0 = fmaf(A5, t1, v0);  v1 = fmaf(A5, t2, v1);  v2 = fmaf(A6, t0, v2);
        // d = 8 : A^8 = a^10*S^2  -> (a^10*t2, a^11*t0, a^11*t1)
        t0 = __shfl_up_sync(FULLM, v0, 8);
        t1 = __shfl_up_sync(FULLM, v1, 8);
        t2 = __shfl_up_sync(FULLM, v2, 8);
        if (lane < 8) { t0 = 0.f; t1 = 0.f; t2 = 0.f; }
        v0 = fmaf(A10, t2, v0); v1 = fmaf(A11, t0, v1); v2 = fmaf(A11, t1, v2);
        // (d = 16 dropped: coefficients ~a^20 ~ 1e-8)

        // ---- apply carry: f = v + A^(k+1) * sc  (permute sc by r) ----
        float p0, p1, p2;
        if (r == 1)      { p0 = sc1; p1 = sc2; p2 = sc0; }
        else if (r == 2) { p0 = sc2; p1 = sc0; p2 = sc1; }
        else             { p0 = sc0; p1 = sc1; p2 = sc2; }
        const float f0 = fmaf(g0, p0, v0);
        const float f1 = fmaf(g1, p1, v1);
        const float f2 = fmaf(g2, p2, v2);

        // ---- exclusive state for this lane's group ----
        float e0 = __shfl_up_sync(FULLM, f0, 1);
        float e1 = __shfl_up_sync(FULLM, f1, 1);
        float e2 = __shfl_up_sync(FULLM, f2, 1);
        if (lane == 0) { e0 = sc0; e1 = sc1; e2 = sc2; }

        // ---- reconstruct the 4 outputs ----
        float4 o;
        o.x = fmaf(A1, e0, WW * x.x);
        o.y = fmaf(A1, e1, WW * x.y);
        o.z = fmaf(A1, e2, WW * x.z);
        o.w = fmaf(A1, o.x, WW * x.w);

        if (valid && i >= i0) dst[q] = o;

        // ---- carry for next iteration = state after lane 31's group ----
        sc0 = __shfl_sync(FULLM, f0, 31);
        sc1 = __shfl_sync(FULLM, f1, 31);
        sc2 = __shfl_sync(FULLM, f2, 31);
    }
}

extern "C" void kernel_launch(void* const* d_in, const int* in_sizes, int n_in,
                              void* d_out, int out_size) {
    const float4* in  = (const float4*)d_in[0];
    float4*       out = (float4*)d_out;
    const int warps = B_DIM * NSEG;                 // 24576
    const int ctas  = (warps * 32 + NT - 1) / NT;   // 3072
    sta_ema_scan_kernel<<<ctas, NT>>>(in, out);
}

// round 8
// speedup vs baseline: 1.2727x; 1.0916x over previous
#include <cuda_runtime.h>
#include <cuda_bf16.h>

// EMA over time for wave[B=4096, T=6000, C=3] fp32, w=0.6, a=1-w=0.4.
//   y[f] = a*y[f-3] + w*x[f]   (per-channel recurrence; y[f<0]=0)
//
// One float4 group g maps 3-float state s -> s' = A s + b(x),
//   A = a*S, S = [[0,1,0],[0,0,1],[a,0,0]], S^3 = a*I
//   b(x) = (w*x1, w*x2, a*w*x0 + w*x3)
// Lane k handles group 32*i + k -> coalesced float4 I/O. Warp affine scan
// (d=1,2,4,8; A^16 ~1e-8 dropped) + per-lane constant carry matrix A^(k+1).
//
// R4: 2x software pipelining. The v-scan (4 shfl stages) is carry-independent;
// compute v for two iterations back-to-back (ILP 2), then run the short serial
// carry tail (fma + shfl31) twice. Halves the exposed per-warp latency chain.

#define A1  0.4f
#define WW  0.6f
#define A2  (A1*A1)
#define A3  (A2*A1)
#define A5  (A2*A3)
#define A6  (A3*A3)
#define A10 (A5*A5)
#define A11 (A5*A6)

#define B_DIM   4096
#define ROW_F4  4500            // 18000 floats / 4 per batch row
#define SEGJ    24              // emit-iterations per warp segment (12 pairs)
#define NSEG    6               // 6*24 = 144 >= ceil(4500/32) = 141
#define NT      256
#define FULLM   0xFFFFFFFFu

// 4-stage affine Hillis-Steele accumulation (carry-independent part).
__device__ __forceinline__ void scan_v(float& v0, float& v1, float& v2, int lane) {
    float t0, t1, t2;
    // d = 1 : A^1 = a*S       -> (a*t1, a*t2, a^2*t0)
    t0 = __shfl_up_sync(FULLM, v0, 1);
    t1 = __shfl_up_sync(FULLM, v1, 1);
    t2 = __shfl_up_sync(FULLM, v2, 1);
    if (lane < 1) { t0 = 0.f; t1 = 0.f; t2 = 0.f; }
    v0 = fmaf(A1, t1, v0);  v1 = fmaf(A1, t2, v1);  v2 = fmaf(A2, t0, v2);
    // d = 2 : A^2 = a^2*S^2   -> (a^2*t2, a^3*t0, a^3*t1)
    t0 = __shfl_up_sync(FULLM, v0, 2);
    t1 = __shfl_up_sync(FULLM, v1, 2);
    t2 = __shfl_up_sync(FULLM, v2, 2);
    if (lane < 2) { t0 = 0.f; t1 = 0.f; t2 = 0.f; }
    v0 = fmaf(A2, t2, v0);  v1 = fmaf(A3, t0, v1);  v2 = fmaf(A3, t1, v2);
    // d = 4 : A^4 = a^5*S     -> (a^5*t1, a^5*t2, a^6*t0)
    t0 = __shfl_up_sync(FULLM, v0, 4);
    t1 = __shfl_up_sync(FULLM, v1, 4);
    t2 = __shfl_up_sync(FULLM, v2, 4);
    if (lane < 4) { t0 = 0.f; t1 = 0.f; t2 = 0.f; }
    v0 = fmaf(A5, t1, v0);  v1 = fmaf(A5, t2, v1);  v2 = fmaf(A6, t0, v2);
    // d = 8 : A^8 = a^10*S^2  -> (a^10*t2, a^11*t0, a^11*t1)
    t0 = __shfl_up_sync(FULLM, v0, 8);
    t1 = __shfl_up_sync(FULLM, v1, 8);
    t2 = __shfl_up_sync(FULLM, v2, 8);
    if (lane < 8) { t0 = 0.f; t1 = 0.f; t2 = 0.f; }
    v0 = fmaf(A10, t2, v0); v1 = fmaf(A11, t0, v1); v2 = fmaf(A11, t1, v2);
}

__global__ __launch_bounds__(NT, 6)
void sta_ema_scan_kernel(const float4* __restrict__ in, float4* __restrict__ out) {
    const int gw   = (blockIdx.x * NT + threadIdx.x) >> 5;   // global warp id
    const int lane = threadIdx.x & 31;
    if (gw >= B_DIM * NSEG) return;

    const int b = gw / NSEG;
    const int s = gw % NSEG;

    const float4* src = in  + (long long)b * ROW_F4;
    float4*       dst = out + (long long)b * ROW_F4;

    const int i0 = SEGJ * s;

    // Per-lane constant carry matrix A^(k+1) = a^(k+1) * S^(k+1),
    // S^(k+1) = a^floor((k+1)/3) * S^((k+1)%3).
    const int  kp = lane + 1;
    const int  m  = kp / 3;
    const int  r  = kp % 3;
    const float gamma = __powf(A1, (float)(kp + m));
    float g0 = gamma, g1 = gamma, g2 = gamma;
    if (r == 1) { g2 *= A1; }
    if (r == 2) { g1 *= A1; g2 *= A1; }

    float sc0 = 0.f, sc1 = 0.f, sc2 = 0.f;

    // ---- warm iteration at i0-1 (uniform for all segments; s=0 loads are
    // out-of-range -> zeros -> carry stays 0, matching sta_{-1}=0) ----
    {
        const int q = 32 * (i0 - 1) + lane;
        float4 x = (q >= 0 && q < ROW_F4) ? src[q] : make_float4(0.f, 0.f, 0.f, 0.f);
        float v0 = WW * x.y;
        float v1 = WW * x.z;
        float v2 = fmaf(A1 * WW, x.x, WW * x.w);
        scan_v(v0, v1, v2, lane);
        float p0, p1, p2;
        if (r == 1)      { p0 = sc1; p1 = sc2; p2 = sc0; }
        else if (r == 2) { p0 = sc2; p1 = sc0; p2 = sc1; }
        else             { p0 = sc0; p1 = sc1; p2 = sc2; }
        const float f0 = fmaf(g0, p0, v0);
        const float f1 = fmaf(g1, p1, v1);
        const float f2 = fmaf(g2, p2, v2);
        sc0 = __shfl_sync(FULLM, f0, 31);
        sc1 = __shfl_sync(FULLM, f1, 31);
        sc2 = __shfl_sync(FULLM, f2, 31);
    }

    // ---- emit loop: 12 pairs of iterations ----
    #pragma unroll 2
    for (int j = 0; j < SEGJ / 2; ++j) {
        const int ia = i0 + 2 * j;
        const int qa = 32 * ia + lane;
        const int qb = qa + 32;
        const bool va_ok = (qa < ROW_F4);
        const bool vb_ok = (qb < ROW_F4);

        float4 xa = va_ok ? src[qa] : make_float4(0.f, 0.f, 0.f, 0.f);
        float4 xb = vb_ok ? src[qb] : make_float4(0.f, 0.f, 0.f, 0.f);

        float a0 = WW * xa.y, a1 = WW * xa.z, a2 = fmaf(A1 * WW, xa.x, WW * xa.w);
        float b0 = WW * xb.y, b1 = WW * xb.z, b2 = fmaf(A1 * WW, xb.x, WW * xb.w);

        // carry-independent scans (back-to-back -> ILP 2 over shfl latency)
        scan_v(a0, a1, a2, lane);
        scan_v(b0, b1, b2, lane);

        // ---- serial tail, iteration a ----
        float p0, p1, p2;
        if (r == 1)      { p0 = sc1; p1 = sc2; p2 = sc0; }
        else if (r == 2) { p0 = sc2; p1 = sc0; p2 = sc1; }
        else             { p0 = sc0; p1 = sc1; p2 = sc2; }
        const float fa0 = fmaf(g0, p0, a0);
        const float fa1 = fmaf(g1, p1, a1);
        const float fa2 = fmaf(g2, p2, a2);

        float ea0 = __shfl_up_sync(FULLM, fa0, 1);
        float ea1 = __shfl_up_sync(FULLM, fa1, 1);
        float ea2 = __shfl_up_sync(FULLM, fa2, 1);
        if (lane == 0) { ea0 = sc0; ea1 = sc1; ea2 = sc2; }

        float4 oa;
        oa.x = fmaf(A1, ea0, WW * xa.x);
        oa.y = fmaf(A1, ea1, WW * xa.y);
        oa.z = fmaf(A1, ea2, WW * xa.z);
        oa.w = fmaf(A1, oa.x, WW * xa.w);
        if (va_ok) dst[qa] = oa;

        const float sb0 = __shfl_sync(FULLM, fa0, 31);
        const float sb1 = __shfl_sync(FULLM, fa1, 31);
        const float sb2 = __shfl_sync(FULLM, fa2, 31);

        // ---- serial tail, iteration b ----
        if (r == 1)      { p0 = sb1; p1 = sb2; p2 = sb0; }
        else if (r == 2) { p0 = sb2; p1 = sb0; p2 = sb1; }
        else             { p0 = sb0; p1 = sb1; p2 = sb2; }
        const float fb0 = fmaf(g0, p0, b0);
        const float fb1 = fmaf(g1, p1, b1);
        const float fb2 = fmaf(g2, p2, b2);

        float eb0 = __shfl_up_sync(FULLM, fb0, 1);
        float eb1 = __shfl_up_sync(FULLM, fb1, 1);
        float eb2 = __shfl_up_sync(FULLM, fb2, 1);
        if (lane == 0) { eb0 = sb0; eb1 = sb1; eb2 = sb2; }

        float4 ob;
        ob.x = fmaf(A1, eb0, WW * xb.x);
        ob.y = fmaf(A1, eb1, WW * xb.y);
        ob.z = fmaf(A1, eb2, WW * xb.z);
        ob.w = fmaf(A1, ob.x, WW * xb.w);
        if (vb_ok) dst[qb] = ob;

        sc0 = __shfl_sync(FULLM, fb0, 31);
        sc1 = __shfl_sync(FULLM, fb1, 31);
        sc2 = __shfl_sync(FULLM, fb2, 31);
    }
}

extern "C" void kernel_launch(void* const* d_in, const int* in_sizes, int n_in,
                              void* d_out, int out_size) {
    const float4* in  = (const float4*)d_in[0];
    float4*       out = (float4*)d_out;
    const int warps = B_DIM * NSEG;                 // 24576
    const int ctas  = (warps * 32 + NT - 1) / NT;   // 3072
    sta_ema_scan_kernel<<<ctas, NT>>>(in, out);
}

// round 10
// speedup vs baseline: 1.2774x; 1.0036x over previous
#include <cuda_runtime.h>
#include <cuda_bf16.h>

// EMA over time for wave[B=4096, T=6000, C=3] fp32, w=0.6, a=1-w=0.4.
//   y[f] = a*y[f-3] + w*x[f]   (per-channel recurrence; y[f<0]=0)
//
// One float4 group g maps 3-float state s -> s' = A s + b(x),
//   A = a*S, S = [[0,1,0],[0,0,1],[a,0,0]], S^3 = a*I
//   b(x) = (w*x1, w*x2, a*w*x0 + w*x3)
// Lane k handles group 32*i + k -> coalesced float4 I/O. Warp affine scan
// with stages d=1,2,4 (A^8 entries ~1e-4 -> dropped; history beyond the
// current iteration is handled EXACTLY by the per-lane carry matrix A^(k+1),
// so truncation only affects intra-iteration distances 8..31: ~1e-4 norm err).
//
// R5: (a) no exclusive shift -- f=(y[4q+1..4q+3]) gives o.y/o.z/o.w directly
// and o.x = (f2 - w*x.w)/a in-lane; (b) depth-2 software pipeline: scan of
// iteration j+1 is carry-independent and issues before the tail of j.

#define A1  0.4f
#define WW  0.6f
#define INVA 2.5f
#define A2  (A1*A1)
#define A3  (A2*A1)
#define A5  (A2*A3)
#define A6  (A3*A3)

#define B_DIM   4096
#define ROW_F4  4500            // 18000 floats / 4 per batch row
#define SEGJ    24              // emit-iterations per warp segment
#define NSEG    6               // 6*24 = 144 >= ceil(4500/32) = 141
#define NT      256
#define FULLM   0xFFFFFFFFu

// b(x) prep
__device__ __forceinline__ void prep_v(const float4& x, float& v0, float& v1, float& v2) {
    v0 = WW * x.y;
    v1 = WW * x.z;
    v2 = fmaf(A1 * WW, x.x, WW * x.w);
}

// 3-stage affine Hillis-Steele accumulation (carry-independent part).
__device__ __forceinline__ void scan_v(float& v0, float& v1, float& v2, int lane) {
    float t0, t1, t2;
    // d = 1 : A^1 = a*S       -> (a*t1, a*t2, a^2*t0)
    t0 = __shfl_up_sync(FULLM, v0, 1);
    t1 = __shfl_up_sync(FULLM, v1, 1);
    t2 = __shfl_up_sync(FULLM, v2, 1);
    if (lane < 1) { t0 = 0.f; t1 = 0.f; t2 = 0.f; }
    v0 = fmaf(A1, t1, v0);  v1 = fmaf(A1, t2, v1);  v2 = fmaf(A2, t0, v2);
    // d = 2 : A^2 = a^2*S^2   -> (a^2*t2, a^3*t0, a^3*t1)
    t0 = __shfl_up_sync(FULLM, v0, 2);
    t1 = __shfl_up_sync(FULLM, v1, 2);
    t2 = __shfl_up_sync(FULLM, v2, 2);
    if (lane < 2) { t0 = 0.f; t1 = 0.f; t2 = 0.f; }
    v0 = fmaf(A2, t2, v0);  v1 = fmaf(A3, t0, v1);  v2 = fmaf(A3, t1, v2);
    // d = 4 : A^4 = a^5*S     -> (a^5*t1, a^5*t2, a^6*t0)
    t0 = __shfl_up_sync(FULLM, v0, 4);
    t1 = __shfl_up_sync(FULLM, v1, 4);
    t2 = __shfl_up_sync(FULLM, v2, 4);
    if (lane < 4) { t0 = 0.f; t1 = 0.f; t2 = 0.f; }
    v0 = fmaf(A5, t1, v0);  v1 = fmaf(A5, t2, v1);  v2 = fmaf(A6, t0, v2);
}

__global__ __launch_bounds__(NT, 5)
void sta_ema_scan_kernel(const float4* __restrict__ in, float4* __restrict__ out) {
    const int gw   = (blockIdx.x * NT + threadIdx.x) >> 5;   // global warp id
    const int lane = threadIdx.x & 31;
    if (gw >= B_DIM * NSEG) return;

    const int b = gw / NSEG;
    const int s = gw % NSEG;

    const float4* src = in  + (long long)b * ROW_F4;
    float4*       dst = out + (long long)b * ROW_F4;

    const int i0 = SEGJ * s;

    // Per-lane constant carry matrix A^(k+1) = a^(k+1) * S^(k+1),
    // S^(k+1) = a^floor((k+1)/3) * S^((k+1)%3).
    const int  kp = lane + 1;
    const int  m  = kp / 3;
    const int  r  = kp % 3;
    const float gamma = __powf(A1, (float)(kp + m));
    float g0 = gamma, g1 = gamma, g2 = gamma;
    if (r == 1) { g2 *= A1; }
    if (r == 2) { g1 *= A1; g2 *= A1; }

    float sc0 = 0.f, sc1 = 0.f, sc2 = 0.f;

    // ---- warm iteration at i0-1 (s=0 loads out-of-range -> zeros) ----
    {
        const int q = 32 * (i0 - 1) + lane;
        float4 x = (q >= 0 && q < ROW_F4) ? src[q] : make_float4(0.f, 0.f, 0.f, 0.f);
        float v0, v1, v2;
        prep_v(x, v0, v1, v2);
        scan_v(v0, v1, v2, lane);
        // carry is zero here; f = v
        sc0 = __shfl_sync(FULLM, v0, 31);
        sc1 = __shfl_sync(FULLM, v1, 31);
        sc2 = __shfl_sync(FULLM, v2, 31);
    }

    // ---- pipeline prologue: iteration i0 ----
    int q0 = 32 * i0 + lane;
    float4 x0 = (q0 < ROW_F4) ? src[q0] : make_float4(0.f, 0.f, 0.f, 0.f);
    float v0, v1, v2;
    prep_v(x0, v0, v1, v2);
    scan_v(v0, v1, v2, lane);

    #pragma unroll 4
    for (int j = 0; j < SEGJ - 1; ++j) {
        // -- prefetch + scan iteration j+1 (carry-independent; overlaps tail) --
        const int q1 = q0 + 32;
        float4 x1 = (q1 < ROW_F4) ? src[q1] : make_float4(0.f, 0.f, 0.f, 0.f);
        float u0, u1, u2;
        prep_v(x1, u0, u1, u2);
        scan_v(u0, u1, u2, lane);

        // -- serial tail for iteration j --
        float p0, p1, p2;
        if (r == 1)      { p0 = sc1; p1 = sc2; p2 = sc0; }
        else if (r == 2) { p0 = sc2; p1 = sc0; p2 = sc1; }
        else             { p0 = sc0; p1 = sc1; p2 = sc2; }
        const float f0 = fmaf(g0, p0, v0);
        const float f1 = fmaf(g1, p1, v1);
        const float f2 = fmaf(g2, p2, v2);

        float4 o;                                   // f = (y[4q+1], y[4q+2], y[4q+3])
        o.x = INVA * fmaf(-WW, x0.w, f2);           // y[4q] = (f2 - w*x3)/a
        o.y = f0;
        o.z = f1;
        o.w = f2;
        if (q0 < ROW_F4) dst[q0] = o;

        sc0 = __shfl_sync(FULLM, f0, 31);
        sc1 = __shfl_sync(FULLM, f1, 31);
        sc2 = __shfl_sync(FULLM, f2, 31);

        // rotate pipeline
        x0 = x1; v0 = u0; v1 = u1; v2 = u2; q0 = q1;
    }

    // ---- epilogue: last iteration's tail ----
    {
        float p0, p1, p2;
        if (r == 1)      { p0 = sc1; p1 = sc2; p2 = sc0; }
        else if (r == 2) { p0 = sc2; p1 = sc0; p2 = sc1; }
        else             { p0 = sc0; p1 = sc1; p2 = sc2; }
        const float f0 = fmaf(g0, p0, v0);
        const float f1 = fmaf(g1, p1, v1);
        const float f2 = fmaf(g2, p2, v2);
        float4 o;
        o.x = INVA * fmaf(-WW, x0.w, f2);
        o.y = f0;
        o.z = f1;
        o.w = f2;
        if (q0 < ROW_F4) dst[q0] = o;
    }
}

extern "C" void kernel_launch(void* const* d_in, const int* in_sizes, int n_in,
                              void* d_out, int out_size) {
    const float4* in  = (const float4*)d_in[0];
    float4*       out = (float4*)d_out;
    const int warps = B_DIM * NSEG;                 // 24576
    const int ctas  = (warps * 32 + NT - 1) / NT;   // 3072
    sta_ema_scan_kernel<<<ctas, NT>>>(in, out);
}